// round 10
// baseline (speedup 1.0000x reference)
#include <cuda_runtime.h>
#include <cuda_bf16.h>

// PointPWC loss, B=1, N=8192.
// total = 0.02*chamfer + 0.006*curv + 0.01*smooth
//
// R9: CHUNKS=1 + inline consume.
//  Each query scans ALL 8192 candidates in one pass -> final top-K lives in
//  registers at scan end, so the epilogues fuse into the pairs kernel:
//   z=0: pc2 self-knn (K=10) -> writes g_c2[i] inline
//   z=1: pc1 self-knn (K=10) -> writes g_moved[i] + accumulates smoothness
//   z=2: warp->pc2    (K=5)  -> accumulates chamfer-fwd, stores 5 (d,id) pairs
//   z=3: pc2->warp min       -> accumulates chamfer-bwd
//  Only tiny scratch remains (top-5 of slice 2 for the cross-curvature kernel,
//  which needs c2/moved produced by slices 0/1 -> separate launch for ordering).
//  Single full scan also kills per-chunk fresh-list insert transients (-40%
//  warp-insert events vs CHUNKS=2), the dominant cost term.

#define MAXN   8192
#define KNN    10
#define KNN5   5
#define TPB    128

__device__ float4 g_pc1[MAXN];
__device__ float4 g_pc2[MAXN];
__device__ float4 g_warp[MAXN];
__device__ float4 g_flow[MAXN];
__device__ float4 g_c2[MAXN];
__device__ float4 g_moved[MAXN];
__device__ float  g_pd5[MAXN * KNN5];   // i-major: [i*5 + t]
__device__ int    g_pi5[MAXN * KNN5];
__device__ double g_acc[4];  // 0: chamfer fwd, 1: chamfer bwd, 2: smooth, 3: curv

__device__ __forceinline__ double warp_red(double v) {
    #pragma unroll
    for (int o = 16; o > 0; o >>= 1)
        v += __shfl_down_sync(0xffffffffu, v, o);
    return v;
}

__global__ void prep_kernel(const float* __restrict__ pred,
                            const float* __restrict__ gt,
                            const float* __restrict__ coords, int n) {
    int i = blockIdx.x * blockDim.x + threadIdx.x;
    if (i == 0) { g_acc[0] = 0.0; g_acc[1] = 0.0; g_acc[2] = 0.0; g_acc[3] = 0.0; }
    if (i >= n) return;
    float cx = coords[3 * i + 0], cy = coords[3 * i + 1], cz = coords[3 * i + 2];
    float gx = gt[3 * i + 0],     gy = gt[3 * i + 1],     gz = gt[3 * i + 2];
    float fx = pred[3 * i + 0],   fy = pred[3 * i + 1],   fz = pred[3 * i + 2];
    float p2x = cx + gx, p2y = cy + gy, p2z = cz + gz;
    float wx  = cx + fx, wy  = cy + fy, wz  = cz + fz;
    g_pc1[i]  = make_float4(cx, cy, cz, cx * cx + cy * cy + cz * cz);
    g_pc2[i]  = make_float4(p2x, p2y, p2z, p2x * p2x + p2y * p2y + p2z * p2z);
    g_warp[i] = make_float4(wx, wy, wz, wx * wx + wy * wy + wz * wz);
    g_flow[i] = make_float4(fx, fy, fz, 0.f);
}

template <int K>
__device__ __forceinline__ void insert_sorted(float dm, int j,
                                              float (&d)[K], int (&id)[K],
                                              float& kth) {
    d[K - 1] = dm; id[K - 1] = j;
    #pragma unroll
    for (int s = K - 1; s > 0; --s) {
        if (d[s] < d[s - 1]) {
            float td = d[s]; d[s] = d[s - 1]; d[s - 1] = td;
            int   ti = id[s]; id[s] = id[s - 1]; id[s - 1] = ti;
        }
    }
    kth = d[K - 1];
}

// Full scan of all n candidates from P, maintaining per-thread sorted top-K of
// dm = |p|^2 - 2<q,p> (true dist = dm + |q|^2; per-query constant shift keeps
// ordering; strict '<' on ascending j keeps earliest index on ties, matching
// lax.top_k).
template <int K>
__device__ __forceinline__ void knn_scan_full(const float4* __restrict__ P,
                                              float4 q, int n, float4* sp,
                                              float (&d)[K], int (&id)[K]) {
    #pragma unroll
    for (int t = 0; t < K; t++) { d[t] = 3.4e38f; id[t] = 0; }
    float kth = 3.4e38f;
    for (int jb = 0; jb < n; jb += TPB) {
        __syncthreads();
        sp[threadIdx.x] = P[jb + threadIdx.x];
        __syncthreads();
        #pragma unroll 8
        for (int t = 0; t < TPB; t++) {
            float4 p = sp[t];
            float dot = fmaf(q.x, p.x, fmaf(q.y, p.y, q.z * p.z));
            float dm  = fmaf(-2.f, dot, p.w);
            if (dm < kth) insert_sorted<K>(dm, jb + t, d, id, kth);
        }
    }
}

// grid = (n/TPB, 1, 4); consume fused into each slice's tail.
__global__ void __launch_bounds__(TPB) pairs_kernel(int n, const int* __restrict__ kptr) {
    __shared__ float4 sp[TPB];
    const int slice = blockIdx.z;
    const int i = blockIdx.x * TPB + threadIdx.x;
    const int ii = (i < n) ? i : 0;

    if (slice == 0) {
        // pc2 self-knn -> curvature of pc2 (inline)
        float4 q = g_pc2[ii];
        float d[KNN]; int id[KNN];
        knn_scan_full<KNN>(g_pc2, q, n, sp, d, id);
        if (i < n) {
            float sx = 0.f, sy = 0.f, sz = 0.f;
            #pragma unroll
            for (int t = 0; t < KNN; t++) {
                float4 p = g_pc2[id[t]];
                sx += p.x; sy += p.y; sz += p.z;
            }
            g_c2[i] = make_float4((sx - 10.f * q.x) / 9.f,
                                  (sy - 10.f * q.y) / 9.f,
                                  (sz - 10.f * q.z) / 9.f, 0.f);
        }
    } else if (slice == 1) {
        // pc1 self-knn -> moved curvature (inline) + smoothness (inline acc)
        float4 q = g_pc1[ii];
        float d[KNN]; int id[KNN];
        knn_scan_full<KNN>(g_pc1, q, n, sp, d, id);
        double sm_d = 0.0;
        if (i < n) {
            float4 w = g_warp[i];
            float sx = 0.f, sy = 0.f, sz = 0.f;
            #pragma unroll
            for (int t = 0; t < KNN; t++) {
                float4 p = g_warp[id[t]];
                sx += p.x; sy += p.y; sz += p.z;
            }
            g_moved[i] = make_float4((sx - 10.f * w.x) / 9.f,
                                     (sy - 10.f * w.y) / 9.f,
                                     (sz - 10.f * w.z) / 9.f, 0.f);
            int k = *kptr;
            float4 f = g_flow[i];
            float sm = 0.f;
            #pragma unroll
            for (int t = 0; t < KNN; t++) {
                if (t < k) {
                    float4 gfl = g_flow[id[t]];
                    float dx = gfl.x - f.x, dy = gfl.y - f.y, dz = gfl.z - f.z;
                    float sq = dx * dx + dy * dy + dz * dz;
                    sm += sqrtf(sq);   // sq==0 (self) -> 0, matches safe-norm
                }
            }
            sm_d = (double)(sm / 8.f);
        }
        double v = warp_red(sm_d);
        if ((threadIdx.x & 31) == 0) atomicAdd(&g_acc[2], v);
    } else if (slice == 2) {
        // warp -> pc2 top-5: chamfer fwd (inline acc) + store top-5 for interp
        float4 q = g_warp[ii];
        float d[KNN5]; int id[KNN5];
        knn_scan_full<KNN5>(g_pc2, q, n, sp, d, id);
        double d1 = 0.0;
        if (i < n) {
            d1 = (double)(d[0] + q.w);
            #pragma unroll
            for (int t = 0; t < KNN5; t++) {
                g_pd5[i * KNN5 + t] = d[t] + q.w;
                g_pi5[i * KNN5 + t] = id[t];
            }
        }
        double v = warp_red(d1);
        if ((threadIdx.x & 31) == 0) atomicAdd(&g_acc[0], v);
    } else {
        // pc2 -> warp min: reverse chamfer (inline acc)
        float4 q = g_pc2[ii];
        float m = 3.4e38f;
        for (int jb = 0; jb < n; jb += TPB) {
            __syncthreads();
            sp[threadIdx.x] = g_warp[jb + threadIdx.x];
            __syncthreads();
            #pragma unroll 8
            for (int t = 0; t < TPB; t++) {
                float4 p = sp[t];
                float dot = fmaf(q.x, p.x, fmaf(q.y, p.y, q.z * p.z));
                float dm  = fmaf(-2.f, dot, p.w);
                m = fminf(m, dm);
            }
        }
        double v = (i < n) ? (double)(m + q.w) : 0.0;
        double s = warp_red(v);
        if ((threadIdx.x & 31) == 0) atomicAdd(&g_acc[1], s);
    }
}

// Interp-curvature loss: needs g_c2 (slice 0) and g_moved (slice 1), hence a
// separate launch after pairs. Reads the tiny i-major top-5 scratch.
__global__ void cross_consume_kernel(int n) {
    int i = blockIdx.x * blockDim.x + threadIdx.x;
    double cv = 0.0;
    if (i < n) {
        float w[KNN5]; float wsum = 0.f;
        int id[KNN5];
        #pragma unroll
        for (int t = 0; t < KNN5; t++) {
            float dist = g_pd5[i * KNN5 + t];
            id[t] = g_pi5[i * KNN5 + t];
            w[t] = 1.f / (dist + 1e-8f);
            wsum += w[t];
        }
        float ix = 0.f, iy = 0.f, iz = 0.f;
        #pragma unroll
        for (int t = 0; t < KNN5; t++) {
            float wn = w[t] / wsum;
            float4 c = g_c2[id[t]];
            ix = fmaf(wn, c.x, ix);
            iy = fmaf(wn, c.y, iy);
            iz = fmaf(wn, c.z, iz);
        }
        float4 m = g_moved[i];
        float ex = ix - m.x, ey = iy - m.y, ez = iz - m.z;
        cv = (double)(ex * ex + ey * ey + ez * ez);
    }
    double v1 = warp_red(cv);
    if ((threadIdx.x & 31) == 0) atomicAdd(&g_acc[3], v1);
}

__global__ void finalize_kernel(float* __restrict__ out) {
    if (threadIdx.x == 0) {
        double chamfer = g_acc[0] + g_acc[1];
        double total = 0.02 * chamfer      // F_CHAMFER * ALPHA0
                     + 0.006 * g_acc[3]    // F_CURVATURE * ALPHA0
                     + 0.01  * g_acc[2];   // F_SMOOTH * ALPHA0
        out[0] = (float)total;
    }
}

extern "C" void kernel_launch(void* const* d_in, const int* in_sizes, int n_in,
                              void* d_out, int out_size) {
    const float* pred   = (const float*)d_in[0];  // registration_pred (1,N,3)
    const float* gt     = (const float*)d_in[1];  // registration_gt   (1,N,3)
    const float* coords = (const float*)d_in[2];  // coords            (N,3)
    const int*   kptr   = (const int*)d_in[3];    // smoothness_k

    int n = in_sizes[2] / 3;   // 8192
    int cb = (n + 255) / 256;

    prep_kernel<<<cb, 256>>>(pred, gt, coords, n);
    pairs_kernel<<<dim3(n / TPB, 1, 4), TPB>>>(n, kptr);
    cross_consume_kernel<<<cb, 256>>>(n);
    finalize_kernel<<<1, 32>>>((float*)d_out);
}